// round 1
// baseline (speedup 1.0000x reference)
#include <cuda_runtime.h>

#define B_SZ 8192
#define T_SZ 32

// Scratch (static device globals; no runtime allocation)
__device__ float d_Tp[27 * 20];           // [mx][k], k = mh*2 + j, k=18,19 zero pad
__device__ float d_To[9];                 // readout tensor
__device__ float d_S[T_SZ * 18 * B_SZ];   // [t][k][b]

__device__ __forceinline__ float2 cmul(float2 a, float2 b) {
    return make_float2(a.x * b.x - a.y * b.y, a.x * b.y + a.y * b.x);
}

// ---------------------------------------------------------------------------
// Precompute: build entangler U (5 qubits) from w_rec, project to monomial
// tensor T (27x9x2), and readout tensor To (9) from w_out.
// ---------------------------------------------------------------------------
__global__ void precompute_kernel(const float* __restrict__ wrec,
                                  const float* __restrict__ wout) {
    __shared__ float2 Us[32][32];     // [col][row] : column col = U @ e_col
    __shared__ float  Ms[2][32][32];  // M_j = Re(U^H D_j U)
    const int tid = threadIdx.x;

    // U = I
    {
        int col = tid >> 5, row = tid & 31;
        Us[col][row] = make_float2(col == row ? 1.f : 0.f, 0.f);
    }
    __syncthreads();

    for (int l = 0; l < 2; l++) {
        // Rot gates on wires 0..4
        for (int w = 0; w < 5; w++) {
            if (tid < 512) {
                int col = tid >> 4, p = tid & 15;
                int mask = 1 << (4 - w);
                int low = mask - 1;
                int i0 = ((p & ~low) << 1) | (p & low);
                int i1 = i0 | mask;
                float phi = wrec[(l * 5 + w) * 3 + 0];
                float th  = wrec[(l * 5 + w) * 3 + 1];
                float om  = wrec[(l * 5 + w) * 3 + 2];
                float c = cosf(0.5f * th), s = sinf(0.5f * th);
                float al = 0.5f * (phi + om), be = 0.5f * (phi - om);
                float ca = cosf(al), sa = sinf(al);
                float cb = cosf(be), sb = sinf(be);
                // rot = [[ep*c, -em*s], [conj(em)*s, conj(ep)*c]]
                // ep = (ca,-sa), em = (cb,sb)
                float2 r00 = make_float2( c * ca, -c * sa);
                float2 r01 = make_float2(-s * cb, -s * sb);
                float2 r10 = make_float2( s * cb, -s * sb);
                float2 r11 = make_float2( c * ca,  c * sa);
                float2 a0 = Us[col][i0], a1 = Us[col][i1];
                float2 n0 = cmul(r00, a0), u01 = cmul(r01, a1);
                n0.x += u01.x; n0.y += u01.y;
                float2 n1 = cmul(r10, a0), u11 = cmul(r11, a1);
                n1.x += u11.x; n1.y += u11.y;
                Us[col][i0] = n0;
                Us[col][i1] = n1;
            }
            __syncthreads();
        }
        // CNOT ring: range r = l % (n-1) + 1
        int rr = (l % 4) + 1;
        for (int w = 0; w < 5; w++) {
            int cw = w, tw = (w + rr) % 5;
            int cm = 1 << (4 - cw), tm = 1 << (4 - tw);
            {
                int col = tid >> 5, row = tid & 31;
                if ((row & cm) && !(row & tm)) {
                    // new[i] = old[perm[i]] with perm = i^tm when control set
                    // -> swap the pair (one thread owns the swap)
                    float2 a = Us[col][row], b2 = Us[col][row | tm];
                    Us[col][row] = b2;
                    Us[col][row | tm] = a;
                }
            }
            __syncthreads();
        }
    }

    // M_j[s][t] = Re( sum_k conj(U[k][s]) * d_j(k) * U[k][t] )
    // wire 3 -> bit 1, wire 4 -> bit 0
    {
        int s = tid >> 5, t = tid & 31;
        float m0 = 0.f, m1 = 0.f;
#pragma unroll
        for (int k = 0; k < 32; k++) {
            float2 us = Us[s][k], ut = Us[t][k];
            float re = us.x * ut.x + us.y * ut.y;
            m0 += ((k >> 1) & 1) ? -re : re;
            m1 += (k & 1) ? -re : re;
        }
        Ms[0][s][t] = m0;
        Ms[1][s][t] = m1;
    }
    __syncthreads();

    // T_j[m] = (1/32) * sum_u sgn(u)*M_j[u][u^xmask]
    // m in base 3 over wires (wire0 major). digit: 0 -> 1, 1 -> cos, 2 -> sin.
    if (tid < 486) {
        int j = tid / 243, m = tid % 243;
        int dg[5];
        {
            int mm = m;
            for (int w = 4; w >= 0; w--) { dg[w] = mm % 3; mm /= 3; }
        }
        int emask = 0, xmask = 0;
        for (int w = 0; w < 5; w++) {
            if (dg[w] == 1) emask |= 1 << (4 - w);
            if (dg[w] == 2) xmask |= 1 << (4 - w);
        }
        float sum = 0.f;
        for (int u = 0; u < 32; u++) {
            float sgn = (__popc(u & emask) & 1) ? -1.f : 1.f;
            sum += sgn * Ms[j][u][u ^ xmask];
        }
        d_Tp[(m / 9) * 20 + (m % 9) * 2 + j] = sum * (1.f / 32.f);
    }
    // zero pad k = 18,19
    if (tid >= 512 && tid < 512 + 54) {
        int i = tid - 512;
        d_Tp[(i >> 1) * 20 + 18 + (i & 1)] = 0.f;
    }

    // Readout: 2-qubit entangler from w_out, expz on wire 0 (bit 1)
    if (tid == 0) {
        float2 V[4][4];  // [col][row]
#pragma unroll
        for (int c2 = 0; c2 < 4; c2++)
#pragma unroll
            for (int r2 = 0; r2 < 4; r2++)
                V[c2][r2] = make_float2(c2 == r2 ? 1.f : 0.f, 0.f);
        for (int l = 0; l < 2; l++) {
            for (int w = 0; w < 2; w++) {
                float phi = wout[(l * 2 + w) * 3 + 0];
                float th  = wout[(l * 2 + w) * 3 + 1];
                float om  = wout[(l * 2 + w) * 3 + 2];
                float c = cosf(0.5f * th), s = sinf(0.5f * th);
                float al = 0.5f * (phi + om), be = 0.5f * (phi - om);
                float ca = cosf(al), sa = sinf(al);
                float cb = cosf(be), sb = sinf(be);
                float2 r00 = make_float2( c * ca, -c * sa);
                float2 r01 = make_float2(-s * cb, -s * sb);
                float2 r10 = make_float2( s * cb, -s * sb);
                float2 r11 = make_float2( c * ca,  c * sa);
                int mask = 1 << (1 - w);
#pragma unroll
                for (int col = 0; col < 4; col++) {
#pragma unroll
                    for (int i0 = 0; i0 < 4; i0++) {
                        if (i0 & mask) continue;
                        int i1 = i0 | mask;
                        float2 a0 = V[col][i0], a1 = V[col][i1];
                        float2 n0 = cmul(r00, a0), u01 = cmul(r01, a1);
                        n0.x += u01.x; n0.y += u01.y;
                        float2 n1 = cmul(r10, a0), u11 = cmul(r11, a1);
                        n1.x += u11.x; n1.y += u11.y;
                        V[col][i0] = n0;
                        V[col][i1] = n1;
                    }
                }
            }
            // CNOT(0,1) then CNOT(1,0)   (r = 1 both layers for n=2)
#pragma unroll
            for (int w = 0; w < 2; w++) {
                int cw = w, tw = (w + 1) & 1;
                int cm = 1 << (1 - cw), tm = 1 << (1 - tw);
#pragma unroll
                for (int col = 0; col < 4; col++)
#pragma unroll
                    for (int row = 0; row < 4; row++)
                        if ((row & cm) && !(row & tm)) {
                            float2 a = V[col][row], b2 = V[col][row | tm];
                            V[col][row] = b2;
                            V[col][row | tm] = a;
                        }
            }
        }
        float Mo[4][4];
#pragma unroll
        for (int s = 0; s < 4; s++)
#pragma unroll
            for (int t = 0; t < 4; t++) {
                float acc = 0.f;
#pragma unroll
                for (int k = 0; k < 4; k++) {
                    float2 vs = V[s][k], vt = V[t][k];
                    float re = vs.x * vt.x + vs.y * vt.y;
                    acc += ((k >> 1) & 1) ? -re : re;
                }
                Mo[s][t] = acc;
            }
#pragma unroll
        for (int m = 0; m < 9; m++) {
            int d0 = m / 3, d1 = m % 3;
            int emask = (d0 == 1 ? 2 : 0) | (d1 == 1 ? 1 : 0);
            int xmask = (d0 == 2 ? 2 : 0) | (d1 == 2 ? 1 : 0);
            float sum = 0.f;
#pragma unroll
            for (int u = 0; u < 4; u++) {
                float sgn = (__popc(u & emask) & 1) ? -1.f : 1.f;
                sum += sgn * Mo[u][u ^ xmask];
            }
            d_To[m] = sum * 0.25f;
        }
    }
}

// ---------------------------------------------------------------------------
// Phase 1: S[t][k][b] = sum_mx P(x[t,b])[mx] * T[mx][k]   (k = mh*2 + j)
// fma.rn.f32x2 packs the two j outputs per FMA; T broadcast from shared.
// ---------------------------------------------------------------------------
__device__ __forceinline__ unsigned long long fma2(unsigned long long a,
                                                   unsigned long long b,
                                                   unsigned long long c) {
    unsigned long long d;
    asm("fma.rn.f32x2 %0, %1, %2, %3;" : "=l"(d) : "l"(a), "l"(b), "l"(c));
    return d;
}
__device__ __forceinline__ unsigned long long pk2(float x) {
    unsigned long long r;
    asm("mov.b64 %0, {%1, %1};" : "=l"(r) : "f"(x));
    return r;
}

__global__ void __launch_bounds__(256) phase1_kernel(const float* __restrict__ x_seq) {
    __shared__ __align__(16) float Ts[27 * 20];
    const int tid = threadIdx.x;
    for (int i = tid; i < 540; i += 256) Ts[i] = d_Tp[i];
    __syncthreads();

    int e = blockIdx.x * 256 + tid;
    int b = e & (B_SZ - 1);
    int t = e >> 13;
    const float* xp = x_seq + ((size_t)t * B_SZ + b) * 3;
    float x0 = xp[0], x1 = xp[1], x2 = xp[2];
    float s0, c0, s1, c1, s2, c2;
    __sincosf(x0, &s0, &c0);
    __sincosf(x1, &s1, &c1);
    __sincosf(x2, &s2, &c2);
    float g0[3] = {1.f, c0, s0};
    float g1[3] = {1.f, c1, s1};
    float g2[3] = {1.f, c2, s2};

    unsigned long long acc[10];
#pragma unroll
    for (int i = 0; i < 10; i++) acc[i] = 0ull;

    unsigned tbase = (unsigned)__cvta_generic_to_shared(Ts);
#pragma unroll
    for (int m0 = 0; m0 < 3; m0++) {
#pragma unroll
        for (int m1 = 0; m1 < 3; m1++) {
            float p01 = g0[m0] * g1[m1];
#pragma unroll
            for (int m2 = 0; m2 < 3; m2++) {
                float p = p01 * g2[m2];
                unsigned long long p2 = pk2(p);
                int mx = (m0 * 3 + m1) * 3 + m2;
                unsigned ra = tbase + mx * 80;
#pragma unroll
                for (int q = 0; q < 5; q++) {
                    unsigned long long t0, t1;
                    asm volatile("ld.shared.v2.b64 {%0,%1}, [%2];"
                                 : "=l"(t0), "=l"(t1) : "r"(ra + q * 16));
                    acc[2 * q]     = fma2(p2, t0, acc[2 * q]);
                    acc[2 * q + 1] = fma2(p2, t1, acc[2 * q + 1]);
                }
            }
        }
    }

    size_t base = (size_t)t * 18 * B_SZ + b;
#pragma unroll
    for (int mh = 0; mh < 9; mh++) {
        float lo, hi;
        asm("mov.b64 {%0,%1}, %2;" : "=f"(lo), "=f"(hi) : "l"(acc[mh]));
        d_S[base + (size_t)(2 * mh) * B_SZ]     = lo;
        d_S[base + (size_t)(2 * mh + 1) * B_SZ] = hi;
    }
}

// ---------------------------------------------------------------------------
// Phase 2: sequential recurrence over T steps + fused readout.
// ---------------------------------------------------------------------------
__global__ void __launch_bounds__(128) phase2_kernel(float* __restrict__ out) {
    int b = blockIdx.x * 128 + threadIdx.x;
    float To[9];
#pragma unroll
    for (int i = 0; i < 9; i++) To[i] = d_To[i];

    float h0 = 0.f, h1 = 0.f;
    float Sc[18];
    const float* Sb = d_S + b;
#pragma unroll
    for (int k = 0; k < 18; k++) Sc[k] = Sb[(size_t)k * B_SZ];

#pragma unroll
    for (int t = 0; t < T_SZ; t++) {
        float Sn[18];
        if (t < T_SZ - 1) {
            const float* p = Sb + (size_t)(t + 1) * 18 * B_SZ;
#pragma unroll
            for (int k = 0; k < 18; k++) Sn[k] = p[(size_t)k * B_SZ];
        }
        float sh0, ch0, sh1, ch1;
        __sincosf(h0, &sh0, &ch0);
        __sincosf(h1, &sh1, &ch1);
        float Q[9];
        Q[0] = 1.f;        Q[1] = ch1;        Q[2] = sh1;
        Q[3] = ch0;        Q[4] = ch0 * ch1;  Q[5] = ch0 * sh1;
        Q[6] = sh0;        Q[7] = sh0 * ch1;  Q[8] = sh0 * sh1;
        float a0 = 0.f, a1 = 0.f;
#pragma unroll
        for (int mh = 0; mh < 9; mh++) {
            a0 += Sc[2 * mh] * Q[mh];
            a1 += Sc[2 * mh + 1] * Q[mh];
        }
        h0 = a0;
        h1 = a1;
        if (t < T_SZ - 1) {
#pragma unroll
            for (int k = 0; k < 18; k++) Sc[k] = Sn[k];
        }
    }

    // Readout
    float sh0, ch0, sh1, ch1;
    __sincosf(h0, &sh0, &ch0);
    __sincosf(h1, &sh1, &ch1);
    float Q[9] = {1.f, ch1, sh1, ch0, ch0 * ch1, ch0 * sh1, sh0, sh0 * ch1, sh0 * sh1};
    float r = 0.f;
#pragma unroll
    for (int m = 0; m < 9; m++) r += To[m] * Q[m];
    out[b] = r;
}

// ---------------------------------------------------------------------------
extern "C" void kernel_launch(void* const* d_in, const int* in_sizes, int n_in,
                              void* d_out, int out_size) {
    const float* x_seq = nullptr;
    const float* w_rec = nullptr;
    const float* w_out = nullptr;
    for (int i = 0; i < n_in; i++) {
        if (in_sizes[i] == T_SZ * B_SZ * 3) x_seq = (const float*)d_in[i];
        else if (in_sizes[i] == 30)         w_rec = (const float*)d_in[i];
        else if (in_sizes[i] == 12)         w_out = (const float*)d_in[i];
    }
    float* out = (float*)d_out;

    precompute_kernel<<<1, 1024>>>(w_rec, w_out);
    phase1_kernel<<<(T_SZ * B_SZ) / 256, 256>>>(x_seq);
    phase2_kernel<<<B_SZ / 128, 128>>>(out);
}

// round 2
// speedup vs baseline: 1.0920x; 1.0920x over previous
#include <cuda_runtime.h>

#define B_SZ 8192
#define T_SZ 32

// Scratch (static device globals; no runtime allocation)
__device__ float d_Tp[27 * 20];           // [mx][k], k = mh*2 + j, k=18,19 zero pad
__device__ float d_To[9];                 // readout tensor
__device__ float d_S[T_SZ * 18 * B_SZ];   // [t][k][b]

__device__ __forceinline__ float2 cmul(float2 a, float2 b) {
    return make_float2(a.x * b.x - a.y * b.y, a.x * b.y + a.y * b.x);
}

// ---------------------------------------------------------------------------
// Precompute: build entangler U (5 qubits) from w_rec, project to monomial
// tensor T (27x9x2), and readout tensor To (9) from w_out.
// Optimized: gates precomputed once (fast intrinsics), CNOT layers fused into
// one permutation, readout parallelized across 9 threads.
// ---------------------------------------------------------------------------
__global__ void __launch_bounds__(1024) precompute_kernel(const float* __restrict__ wrec,
                                                          const float* __restrict__ wout) {
    __shared__ float2 G[10][4];       // entangler rot gates [l*5+w][r00,r01,r10,r11]
    __shared__ float2 Us[32][32];     // [col][row] : column col = U @ e_col
    __shared__ float  Ms[2][32][32];  // M_j = Re(U^H D_j U)
    const int tid = threadIdx.x;

    // Precompute the 10 rot-gate matrices (one thread each, fast intrinsics)
    if (tid < 10) {
        float phi = wrec[tid * 3 + 0];
        float th  = wrec[tid * 3 + 1];
        float om  = wrec[tid * 3 + 2];
        float s, c, sa, ca, sb, cb;
        __sincosf(0.5f * th, &s, &c);
        __sincosf(0.5f * (phi + om), &sa, &ca);
        __sincosf(0.5f * (phi - om), &sb, &cb);
        G[tid][0] = make_float2( c * ca, -c * sa);
        G[tid][1] = make_float2(-s * cb, -s * sb);
        G[tid][2] = make_float2( s * cb, -s * sb);
        G[tid][3] = make_float2( c * ca,  c * sa);
    }
    // U = I
    {
        int col = tid >> 5, row = tid & 31;
        Us[col][row] = make_float2(col == row ? 1.f : 0.f, 0.f);
    }
    __syncthreads();

#pragma unroll
    for (int l = 0; l < 2; l++) {
        // Rot gates on wires 0..4 (gates read from shared)
#pragma unroll
        for (int w = 0; w < 5; w++) {
            if (tid < 512) {
                int col = tid >> 4, p = tid & 15;
                int mask = 1 << (4 - w);
                int low = mask - 1;
                int i0 = ((p & ~low) << 1) | (p & low);
                int i1 = i0 | mask;
                float2 r00 = G[l * 5 + w][0], r01 = G[l * 5 + w][1];
                float2 r10 = G[l * 5 + w][2], r11 = G[l * 5 + w][3];
                float2 a0 = Us[col][i0], a1 = Us[col][i1];
                float2 n0 = cmul(r00, a0), u01 = cmul(r01, a1);
                n0.x += u01.x; n0.y += u01.y;
                float2 n1 = cmul(r10, a0), u11 = cmul(r11, a1);
                n1.x += u11.x; n1.y += u11.y;
                Us[col][i0] = n0;
                Us[col][i1] = n1;
            }
            __syncthreads();
        }
        // CNOT ring (range r = l+1), 5 CNOTs composed into ONE permutation:
        // s_5[i] = s_0[p0[p1[p2[p3[p4[i]]]]]]
        {
            int col = tid >> 5, row = tid & 31;
            int rr = l + 1;
            int j = row;
#pragma unroll
            for (int w = 4; w >= 0; w--) {
                int cm = 1 << (4 - w);
                int tm = 1 << (4 - ((w + rr) % 5));
                if (j & cm) j ^= tm;
            }
            float2 v = Us[col][j];
            __syncthreads();
            Us[col][row] = v;
        }
        __syncthreads();
    }

    // M_j[s][t] = Re( sum_k conj(U[k][s]) * d_j(k) * U[k][t] )
    // wire 3 -> bit 1, wire 4 -> bit 0
    {
        int s = tid >> 5, t = tid & 31;
        float m0 = 0.f, m1 = 0.f;
#pragma unroll
        for (int k = 0; k < 32; k++) {
            float2 us = Us[s][k], ut = Us[t][k];
            float re = us.x * ut.x + us.y * ut.y;
            m0 += ((k >> 1) & 1) ? -re : re;
            m1 += (k & 1) ? -re : re;
        }
        Ms[0][s][t] = m0;
        Ms[1][s][t] = m1;
    }
    __syncthreads();

    // T_j[m] = (1/32) * sum_u sgn(u)*M_j[u][u^xmask]
    // m in base 3 over wires (wire0 major). digit: 0 -> 1, 1 -> cos, 2 -> sin.
    if (tid < 486) {
        int j = tid / 243, m = tid % 243;
        int dg[5];
        {
            int mm = m;
            for (int w = 4; w >= 0; w--) { dg[w] = mm % 3; mm /= 3; }
        }
        int emask = 0, xmask = 0;
        for (int w = 0; w < 5; w++) {
            if (dg[w] == 1) emask |= 1 << (4 - w);
            if (dg[w] == 2) xmask |= 1 << (4 - w);
        }
        float sum = 0.f;
        for (int u = 0; u < 32; u++) {
            float sgn = (__popc(u & emask) & 1) ? -1.f : 1.f;
            sum += sgn * Ms[j][u][u ^ xmask];
        }
        d_Tp[(m / 9) * 20 + (m % 9) * 2 + j] = sum * (1.f / 32.f);
    }
    // zero pad k = 18,19  (thread range disjoint from T calc and readout)
    if (tid >= 640 && tid < 640 + 54) {
        int i = tid - 640;
        d_Tp[(i >> 1) * 20 + 18 + (i & 1)] = 0.f;
    }

    // Readout: 2-qubit entangler from w_out, expz on wire 0 (bit 1).
    // 9 threads (one per monomial m) each build V redundantly with fast
    // intrinsics — runs concurrently with the T-tensor computation above.
    if (tid >= 512 && tid < 521) {
        int m = tid - 512;
        float2 V[4][4];  // [col][row]
#pragma unroll
        for (int c2 = 0; c2 < 4; c2++)
#pragma unroll
            for (int r2 = 0; r2 < 4; r2++)
                V[c2][r2] = make_float2(c2 == r2 ? 1.f : 0.f, 0.f);
#pragma unroll
        for (int l = 0; l < 2; l++) {
#pragma unroll
            for (int w = 0; w < 2; w++) {
                float phi = wout[(l * 2 + w) * 3 + 0];
                float th  = wout[(l * 2 + w) * 3 + 1];
                float om  = wout[(l * 2 + w) * 3 + 2];
                float s, c, sa, ca, sb, cb;
                __sincosf(0.5f * th, &s, &c);
                __sincosf(0.5f * (phi + om), &sa, &ca);
                __sincosf(0.5f * (phi - om), &sb, &cb);
                float2 r00 = make_float2( c * ca, -c * sa);
                float2 r01 = make_float2(-s * cb, -s * sb);
                float2 r10 = make_float2( s * cb, -s * sb);
                float2 r11 = make_float2( c * ca,  c * sa);
                int mask = 1 << (1 - w);
#pragma unroll
                for (int col = 0; col < 4; col++) {
#pragma unroll
                    for (int i0 = 0; i0 < 4; i0++) {
                        if (i0 & mask) continue;
                        int i1 = i0 | mask;
                        float2 a0 = V[col][i0], a1 = V[col][i1];
                        float2 n0 = cmul(r00, a0), u01 = cmul(r01, a1);
                        n0.x += u01.x; n0.y += u01.y;
                        float2 n1 = cmul(r10, a0), u11 = cmul(r11, a1);
                        n1.x += u11.x; n1.y += u11.y;
                        V[col][i0] = n0;
                        V[col][i1] = n1;
                    }
                }
            }
            // CNOT(0,1) then CNOT(1,0)   (r = 1 both layers for n=2)
#pragma unroll
            for (int w = 0; w < 2; w++) {
                int cw = w, tw = (w + 1) & 1;
                int cm = 1 << (1 - cw), tm = 1 << (1 - tw);
#pragma unroll
                for (int col = 0; col < 4; col++)
#pragma unroll
                    for (int row = 0; row < 4; row++)
                        if ((row & cm) && !(row & tm)) {
                            float2 a = V[col][row], b2 = V[col][row | tm];
                            V[col][row] = b2;
                            V[col][row | tm] = a;
                        }
            }
        }
        // Mo[s][t] for this thread's monomial only (needs full Mo row set)
        float Mo[4][4];
#pragma unroll
        for (int s = 0; s < 4; s++)
#pragma unroll
            for (int t = 0; t < 4; t++) {
                float acc = 0.f;
#pragma unroll
                for (int k = 0; k < 4; k++) {
                    float2 vs = V[s][k], vt = V[t][k];
                    float re = vs.x * vt.x + vs.y * vt.y;
                    acc += ((k >> 1) & 1) ? -re : re;
                }
                Mo[s][t] = acc;
            }
        int d0 = m / 3, d1 = m % 3;
        int emask = (d0 == 1 ? 2 : 0) | (d1 == 1 ? 1 : 0);
        int xmask = (d0 == 2 ? 2 : 0) | (d1 == 2 ? 1 : 0);
        float sum = 0.f;
#pragma unroll
        for (int u = 0; u < 4; u++) {
            float sgn = (__popc(u & emask) & 1) ? -1.f : 1.f;
            sum += sgn * Mo[u][u ^ xmask];
        }
        d_To[m] = sum * 0.25f;
    }
}

// ---------------------------------------------------------------------------
// Phase 1: S[t][k][b] = sum_mx P(x[t,b])[mx] * T[mx][k]   (k = mh*2 + j)
// fma.rn.f32x2 packs the two j outputs per FMA; T broadcast from shared.
// ---------------------------------------------------------------------------
__device__ __forceinline__ unsigned long long fma2(unsigned long long a,
                                                   unsigned long long b,
                                                   unsigned long long c) {
    unsigned long long d;
    asm("fma.rn.f32x2 %0, %1, %2, %3;" : "=l"(d) : "l"(a), "l"(b), "l"(c));
    return d;
}
__device__ __forceinline__ unsigned long long pk2(float x) {
    unsigned long long r;
    asm("mov.b64 %0, {%1, %1};" : "=l"(r) : "f"(x));
    return r;
}

__global__ void __launch_bounds__(256) phase1_kernel(const float* __restrict__ x_seq) {
    __shared__ __align__(16) float Ts[27 * 20];
    const int tid = threadIdx.x;
    for (int i = tid; i < 540; i += 256) Ts[i] = d_Tp[i];
    __syncthreads();

    int e = blockIdx.x * 256 + tid;
    int b = e & (B_SZ - 1);
    int t = e >> 13;
    const float* xp = x_seq + ((size_t)t * B_SZ + b) * 3;
    float x0 = xp[0], x1 = xp[1], x2 = xp[2];
    float s0, c0, s1, c1, s2, c2;
    __sincosf(x0, &s0, &c0);
    __sincosf(x1, &s1, &c1);
    __sincosf(x2, &s2, &c2);
    float g0[3] = {1.f, c0, s0};
    float g1[3] = {1.f, c1, s1};
    float g2[3] = {1.f, c2, s2};

    unsigned long long acc[10];
#pragma unroll
    for (int i = 0; i < 10; i++) acc[i] = 0ull;

    unsigned tbase = (unsigned)__cvta_generic_to_shared(Ts);
#pragma unroll
    for (int m0 = 0; m0 < 3; m0++) {
#pragma unroll
        for (int m1 = 0; m1 < 3; m1++) {
            float p01 = g0[m0] * g1[m1];
#pragma unroll
            for (int m2 = 0; m2 < 3; m2++) {
                float p = p01 * g2[m2];
                unsigned long long p2 = pk2(p);
                int mx = (m0 * 3 + m1) * 3 + m2;
                unsigned ra = tbase + mx * 80;
#pragma unroll
                for (int q = 0; q < 5; q++) {
                    unsigned long long t0, t1;
                    asm volatile("ld.shared.v2.b64 {%0,%1}, [%2];"
                                 : "=l"(t0), "=l"(t1) : "r"(ra + q * 16));
                    acc[2 * q]     = fma2(p2, t0, acc[2 * q]);
                    acc[2 * q + 1] = fma2(p2, t1, acc[2 * q + 1]);
                }
            }
        }
    }

    size_t base = (size_t)t * 18 * B_SZ + b;
#pragma unroll
    for (int mh = 0; mh < 9; mh++) {
        float lo, hi;
        asm("mov.b64 {%0,%1}, %2;" : "=f"(lo), "=f"(hi) : "l"(acc[mh]));
        d_S[base + (size_t)(2 * mh) * B_SZ]     = lo;
        d_S[base + (size_t)(2 * mh + 1) * B_SZ] = hi;
    }
}

// ---------------------------------------------------------------------------
// Phase 2: sequential recurrence over T steps + fused readout.
// ---------------------------------------------------------------------------
__global__ void __launch_bounds__(128) phase2_kernel(float* __restrict__ out) {
    int b = blockIdx.x * 128 + threadIdx.x;
    float To[9];
#pragma unroll
    for (int i = 0; i < 9; i++) To[i] = d_To[i];

    float h0 = 0.f, h1 = 0.f;
    float Sc[18];
    const float* Sb = d_S + b;
#pragma unroll
    for (int k = 0; k < 18; k++) Sc[k] = Sb[(size_t)k * B_SZ];

#pragma unroll
    for (int t = 0; t < T_SZ; t++) {
        float Sn[18];
        if (t < T_SZ - 1) {
            const float* p = Sb + (size_t)(t + 1) * 18 * B_SZ;
#pragma unroll
            for (int k = 0; k < 18; k++) Sn[k] = p[(size_t)k * B_SZ];
        }
        float sh0, ch0, sh1, ch1;
        __sincosf(h0, &sh0, &ch0);
        __sincosf(h1, &sh1, &ch1);
        float Q[9];
        Q[0] = 1.f;        Q[1] = ch1;        Q[2] = sh1;
        Q[3] = ch0;        Q[4] = ch0 * ch1;  Q[5] = ch0 * sh1;
        Q[6] = sh0;        Q[7] = sh0 * ch1;  Q[8] = sh0 * sh1;
        float a0 = 0.f, a1 = 0.f;
#pragma unroll
        for (int mh = 0; mh < 9; mh++) {
            a0 += Sc[2 * mh] * Q[mh];
            a1 += Sc[2 * mh + 1] * Q[mh];
        }
        h0 = a0;
        h1 = a1;
        if (t < T_SZ - 1) {
#pragma unroll
            for (int k = 0; k < 18; k++) Sc[k] = Sn[k];
        }
    }

    // Readout
    float sh0, ch0, sh1, ch1;
    __sincosf(h0, &sh0, &ch0);
    __sincosf(h1, &sh1, &ch1);
    float Q[9] = {1.f, ch1, sh1, ch0, ch0 * ch1, ch0 * sh1, sh0, sh0 * ch1, sh0 * sh1};
    float r = 0.f;
#pragma unroll
    for (int m = 0; m < 9; m++) r += To[m] * Q[m];
    out[b] = r;
}

// ---------------------------------------------------------------------------
extern "C" void kernel_launch(void* const* d_in, const int* in_sizes, int n_in,
                              void* d_out, int out_size) {
    const float* x_seq = nullptr;
    const float* w_rec = nullptr;
    const float* w_out = nullptr;
    for (int i = 0; i < n_in; i++) {
        if (in_sizes[i] == T_SZ * B_SZ * 3) x_seq = (const float*)d_in[i];
        else if (in_sizes[i] == 30)         w_rec = (const float*)d_in[i];
        else if (in_sizes[i] == 12)         w_out = (const float*)d_in[i];
    }
    float* out = (float*)d_out;

    precompute_kernel<<<1, 1024>>>(w_rec, w_out);
    phase1_kernel<<<(T_SZ * B_SZ) / 256, 256>>>(x_seq);
    phase2_kernel<<<B_SZ / 128, 128>>>(out);
}